// round 1
// baseline (speedup 1.0000x reference)
#include <cuda_runtime.h>
#include <cuda_bf16.h>
#include <cstdint>

// Problem constants (32,4,512,512) float32 -> out [32,4] float32
#define ROWS      128
#define N_PER_ROW (512*512)   // 262144
#define K_SEL     5243        // round(262144 * 0.02)
#define CAND_CAP  16384
#define NT        512

// ---- scratch (static device globals; no allocation in kernel_launch) ----
__device__ float g_cand[(size_t)ROWS * CAND_CAP];
__device__ int   g_cand_cnt[ROWS];
__device__ int   g_meta_bucket[ROWS];
__device__ int   g_meta_r[ROWS];
__device__ float g_meta_S[ROWS];
__device__ int   g_meta_flag[ROWS];

// Monotonic key transform: larger float -> larger uint key (handles negatives)
__device__ __forceinline__ unsigned mono(unsigned x) {
    return (x & 0x80000000u) ? ~x : (x | 0x80000000u);
}
__device__ __forceinline__ float unmono(unsigned k) {
    unsigned b = (k & 0x80000000u) ? (k ^ 0x80000000u) : ~k;
    return __uint_as_float(b);
}

// key boundaries
#define KEY_1_0  0xBF800000u   // mono(1.0f)
#define KEY_1_75 0xBFE00000u   // mono(1.75f)
#define BKT_1_0  (KEY_1_0  >> 20)   // 3064
#define BKT_1_75 (KEY_1_75 >> 20)   // 3070

template<int NB>
__device__ __forceinline__ void hist_clear(unsigned* cnt, float* sum) {
    for (int i = threadIdx.x; i < NB; i += NT) { cnt[i] = 0u; sum[i] = 0.f; }
}

template<int NB>
__device__ __forceinline__ void hist_pass(const float* __restrict__ src, int n,
                                          unsigned pmask, unsigned pval, int shift,
                                          unsigned* cnt, float* sum) {
    for (int i = threadIdx.x; i < n; i += NT) {
        float v = src[i];
        unsigned k = mono(__float_as_uint(v));
        if ((k & pmask) == pval) {
            unsigned d = (k >> shift) & (NB - 1);
            atomicAdd(&cnt[d], 1u);
            atomicAdd(&sum[d], v);
        }
    }
}

// Find bucket b with countAbove(b) < r <= countAbove(b)+cnt[b].
// On return: *s_above = strict-above count, *s_sab = strict-above sum.
// Returns -1 if total < r.
template<int NB>
__device__ int radix_select_step(unsigned* cnt, float* sum, int r,
                                 unsigned* s_above, float* s_sab,
                                 unsigned* part, int* s_selb) {
    const int t = threadIdx.x;
    constexpr int PB = NB / NT;
    if (t == 0) { *s_selb = -1; *s_above = 0u; *s_sab = 0.f; }
    __syncthreads();
    unsigned p = 0;
#pragma unroll
    for (int i = 0; i < PB; i++) p += cnt[t * PB + i];
    part[t] = p;
    __syncthreads();
    // inclusive suffix scan over thread partials (Hillis-Steele)
    for (int d = 1; d < NT; d <<= 1) {
        unsigned v = part[t] + ((t + d < NT) ? part[t + d] : 0u);
        __syncthreads();
        part[t] = v;
        __syncthreads();
    }
    unsigned above = (t + 1 < NT) ? part[t + 1] : 0u;  // count in buckets beyond my chunk
    unsigned ur = (unsigned)r;
#pragma unroll
    for (int i = PB - 1; i >= 0; i--) {
        int b = t * PB + i;
        unsigned c = cnt[b];
        if (above < ur && ur <= above + c) { *s_selb = b; *s_above = above; }
        above += c;
    }
    __syncthreads();
    int b = *s_selb;
    if (b >= 0) {
        float loc = 0.f;
        for (int i = t; i < NB; i += NT)
            if (i > b) loc += sum[i];
        if (loc != 0.f) atomicAdd(s_sab, loc);
    }
    __syncthreads();
    return b;
}

// ---- Kernel 1: per-row 12-bit histogram (counts+sums, values >= 1.0),
//      candidate stash (values >= 1.75), and coarse select. Single full read.
__global__ void __launch_bounds__(NT) toptk_hist_kernel(const float* __restrict__ cam) {
    __shared__ unsigned s_cnt[4096];
    __shared__ float    s_sum[4096];
    __shared__ unsigned s_part[NT];
    __shared__ int      s_selb;
    __shared__ unsigned s_above;
    __shared__ float    s_sab;
    __shared__ int      s_cc;

    const int row = blockIdx.x;
    const float4* src = (const float4*)(cam + (size_t)row * N_PER_ROW);
    float* cand = g_cand + (size_t)row * CAND_CAP;

    hist_clear<4096>(s_cnt, s_sum);
    if (threadIdx.x == 0) s_cc = 0;
    __syncthreads();

    // 2 independent float4 loads per iteration for MLP
    const int NV4 = N_PER_ROW / 4;  // 65536
    for (int i = threadIdx.x; i < NV4; i += 2 * NT) {
        float4 v0 = src[i];
        float4 v1 = src[i + NT];
        float a[8] = {v0.x, v0.y, v0.z, v0.w, v1.x, v1.y, v1.z, v1.w};
#pragma unroll
        for (int j = 0; j < 8; j++) {
            unsigned k = mono(__float_as_uint(a[j]));
            if (k >= KEY_1_0) {
                unsigned b = k >> 20;
                atomicAdd(&s_cnt[b], 1u);
                atomicAdd(&s_sum[b], a[j]);
                if (k >= KEY_1_75) {
                    int p = atomicAdd(&s_cc, 1);
                    if (p < CAND_CAP) cand[p] = a[j];
                }
            }
        }
    }
    __syncthreads();

    int b = radix_select_step<4096>(s_cnt, s_sum, K_SEL, &s_above, &s_sab, s_part, &s_selb);

    if (threadIdx.x == 0) {
        int cc = s_cc;
        int flag = 0;
        if (b < 0) flag = 2;                                    // threshold < 1.0: full fallback
        else if (b < (int)BKT_1_75 || cc > CAND_CAP) flag = 1;  // candidates unusable: row fallback
        g_meta_bucket[row] = b;
        g_meta_r[row]      = K_SEL - (int)s_above;
        g_meta_S[row]      = s_sab;
        g_meta_flag[row]   = flag;
        g_cand_cnt[row]    = cc < CAND_CAP ? cc : CAND_CAP;
    }
}

// ---- Kernel 2: refine threshold to exact 32-bit key over candidates (fast path)
//      or full row (fallback), then emit mean.
__global__ void __launch_bounds__(NT) toptk_select_kernel(const float* __restrict__ cam,
                                                          float* __restrict__ out) {
    __shared__ unsigned s_cnt[4096];
    __shared__ float    s_sum[4096];
    __shared__ unsigned s_part[NT];
    __shared__ int      s_selb;
    __shared__ unsigned s_above;
    __shared__ float    s_sab;

    const int row = blockIdx.x;
    const int flag = g_meta_flag[row];
    const float* rowp = cam + (size_t)row * N_PER_ROW;

    const float* src;
    int n, B, r;
    float S;

    if (flag == 2) {
        // exact full-row coarse round (all keys, incl. negatives)
        hist_clear<4096>(s_cnt, s_sum);
        __syncthreads();
        hist_pass<4096>(rowp, N_PER_ROW, 0u, 0u, 20, s_cnt, s_sum);
        __syncthreads();
        B = radix_select_step<4096>(s_cnt, s_sum, K_SEL, &s_above, &s_sab, s_part, &s_selb);
        S = s_sab;
        r = K_SEL - (int)s_above;
        src = rowp; n = N_PER_ROW;
    } else {
        B = g_meta_bucket[row];
        S = g_meta_S[row];
        r = g_meta_r[row];
        if (flag == 1) { src = rowp; n = N_PER_ROW; }
        else           { src = g_cand + (size_t)row * CAND_CAP; n = g_cand_cnt[row]; }
    }

    unsigned prefix = ((unsigned)B) << 20;

    // round 2: bits [10,20)
    __syncthreads();
    hist_clear<1024>(s_cnt, s_sum);
    __syncthreads();
    hist_pass<1024>(src, n, 0xFFF00000u, prefix, 10, s_cnt, s_sum);
    __syncthreads();
    int d1 = radix_select_step<1024>(s_cnt, s_sum, r, &s_above, &s_sab, s_part, &s_selb);
    S += s_sab;
    r -= (int)s_above;
    prefix |= ((unsigned)d1) << 10;

    // round 3: bits [0,10)
    __syncthreads();
    hist_clear<1024>(s_cnt, s_sum);
    __syncthreads();
    hist_pass<1024>(src, n, 0xFFFFFC00u, prefix, 0, s_cnt, s_sum);
    __syncthreads();
    int d2 = radix_select_step<1024>(s_cnt, s_sum, r, &s_above, &s_sab, s_part, &s_selb);
    S += s_sab;
    r -= (int)s_above;
    prefix |= (unsigned)d2;

    float vt = unmono(prefix);  // exact k-th largest value; remaining r ties equal vt
    if (threadIdx.x == 0)
        out[row] = (S + (float)r * vt) / (float)K_SEL;
}

extern "C" void kernel_launch(void* const* d_in, const int* in_sizes, int n_in,
                              void* d_out, int out_size) {
    const float* cam = (const float*)d_in[0];
    float* out = (float*)d_out;
    toptk_hist_kernel<<<ROWS, NT>>>(cam);
    toptk_select_kernel<<<ROWS, NT>>>(cam, out);
}